// round 17
// baseline (speedup 1.0000x reference)
#include <cuda_runtime.h>
#include <cuda_bf16.h>

typedef unsigned int u32;
typedef unsigned long long u64;

#define NN 16384
#define HH 4
#define DD 64
#define BB 512
#define KK 8
#define NQ (2*BB)          // queries = edges flat [src | dst]
#define NROWS (NQ*HH)      // 4096 query-head rows
#define RPB 128            // rows per block = 8 warps x 16
#define NPART 32
#define CPART (NN/NPART)   // 512 candidates per partition
#define CT 128             // candidates per tile (double-buffered, aliased)
#define NTILES (CPART/CT)  // 4
#define SROW 144           // smem row stride bytes (128 data + 16 pad)
#define RL 4               // per-lane list length (quad union 16 >= top-9)

__device__ __nv_bfloat16 g_bpos[(size_t)HH*NN*DD];  // bf16 pos*16, [h][n][d]
__device__ __nv_bfloat16 g_bq[(size_t)HH*NQ*DD];    // gathered query rows
__device__ float g_pk[HH*NN];                        // 131072 - 128*|p|^2
__device__ int   g_knn[NQ*HH*KK];
__device__ u32   g_pp[(size_t)NPART*NQ*HH*9];        // packed partition top-9

__device__ __forceinline__ u32 smem_u32(const void* p) {
    u32 a;
    asm("{ .reg .u64 t; cvta.to.shared.u64 t, %1; cvt.u32.u64 %0, t; }"
        : "=r"(a) : "l"(p));
    return a;
}

// async GMEM->SMEM copies (sm_80 baseline PTX; LDGSTS on sm_103)
__device__ __forceinline__ void cp16(u32 saddr, const void* g) {
    asm volatile("cp.async.cg.shared.global [%0], [%1], 16;" :: "r"(saddr), "l"(g));
}
__device__ __forceinline__ void cp4(u32 saddr, const void* g) {
    asm volatile("cp.async.ca.shared.global [%0], [%1], 4;" :: "r"(saddr), "l"(g));
}
#define CP_COMMIT() asm volatile("cp.async.commit_group;" ::: "memory")
#define CP_WAIT0()  asm volatile("cp.async.wait_group 0;" ::: "memory")
#define CP_WAIT1()  asm volatile("cp.async.wait_group 1;" ::: "memory")

// 4-deep packed sorted insert: single-u32 compares/selects, compile-time indexed.
#define INSERT4(L, pk) do {                                                    \
    if ((pk) > L[3]) {                                                         \
        L[3] = (pk);                                                           \
        { u32 _a = L[2], _b = L[3];                                            \
          L[2] = (_b > _a) ? _b : _a;  L[3] = (_b > _a) ? _a : _b; }           \
        { u32 _a = L[1], _b = L[2];                                            \
          L[1] = (_b > _a) ? _b : _a;  L[2] = (_b > _a) ? _a : _b; }           \
        { u32 _a = L[0], _b = L[1];                                            \
          L[0] = (_b > _a) ? _b : _a;  L[1] = (_b > _a) ? _a : _b; }           \
    }                                                                          \
} while (0)

// 9-deep packed insert.
#define INSERT9P(L, pk) do {                                                   \
    if ((pk) > L[8]) {                                                         \
        L[8] = (pk);                                                           \
        _Pragma("unroll")                                                      \
        for (int _i = 8; _i > 0; _i--)                                         \
            if (L[_i] > L[_i-1]) { u32 _t = L[_i]; L[_i] = L[_i-1]; L[_i-1] = _t; } \
    }                                                                          \
} while (0)

// quad (4-lane) merge of packed lists -> partition top-9, sorted desc.
#define WARP_MERGE(L, whichoff) do {                                           \
    int rowg = rowA + (whichoff)*8;                                            \
    int q = rowg % NQ;                                                         \
    long base = ((long)(part*NQ + q)*HH + h)*9;                                \
    for (int r = 0; r < 9; r++) {                                              \
        u32 v = L[0];                                                          \
        u32 bv = v;                                                            \
        _Pragma("unroll")                                                      \
        for (int o = 1; o < 4; o <<= 1) {                                      \
            u32 ov = __shfl_xor_sync(0xffffffffu, bv, o);                      \
            if (ov > bv) bv = ov;                                              \
        }                                                                      \
        if (v == bv) {                                                         \
            _Pragma("unroll")                                                  \
            for (int _j = 0; _j < RL-1; _j++) L[_j] = L[_j+1];                 \
            L[RL-1] = 0u;                                                      \
        }                                                                      \
        if ((l & 3) == 0) g_pp[base + r] = bv;                                 \
    }                                                                          \
} while (0)

// async stage of one 128-candidate tile into buffer buf_ (CT*8 = 1024 = 4*256).
#define STAGE(tile_, buf_) do {                                                \
    const int _cb = part*CPART + (tile_)*CT;                                   \
    _Pragma("unroll")                                                          \
    for (int _k = 0; _k < 4; _k++) {                                           \
        int _idx = t + 256*_k;                                                 \
        int _r = _idx >> 3, _c = _idx & 7;                                     \
        cp16(smem_u32(&s_mem[buf_][_r*SROW + _c*16]),                          \
             (const char*)(bpos + (size_t)(_cb + _r)*DD) + _c*16);             \
    }                                                                          \
    if (t < CT) cp4(smem_u32(&s_pn2[buf_][t]), &g_pk[h*NN + _cb + t]);         \
    CP_COMMIT();                                                               \
} while (0)

// ---------------------------------------------------------------- kernels 1a/1b
// pos -> bf16 pos*16 [h][n][d]; bias 131072 - 128*|p|^2. Split in halves so
// knn_mma stays at launch slot #4 (ncu capture alignment) with useful work.
__device__ __forceinline__ void prep_body(const float* __restrict__ pos, int gid) {
    int row = gid >> 4;                          // row = n*HH + h
    int f   = gid & 15;
    int n = row >> 2, h = row & 3;
    float4 v = ((const float4*)pos)[(size_t)row*16 + f];
    __nv_bfloat162 b0 = __floats2bfloat162_rn(16.f*v.x, 16.f*v.y);
    __nv_bfloat162 b1 = __floats2bfloat162_rn(16.f*v.z, 16.f*v.w);
    uint2 pk; pk.x = *(u32*)&b0; pk.y = *(u32*)&b1;
    *(uint2*)&g_bpos[((size_t)h*NN + n)*DD + 4*f] = pk;
    float s = v.x*v.x + v.y*v.y + v.z*v.z + v.w*v.w;
#pragma unroll
    for (int o = 1; o < 16; o <<= 1) s += __shfl_xor_sync(0xffffffffu, s, o);
    if (f == 0) g_pk[h*NN + n] = fmaf(s, -128.f, 131072.f);
}
__global__ __launch_bounds__(256) void prep_a(const float* __restrict__ pos) {
    prep_body(pos, blockIdx.x*256 + threadIdx.x);
}
__global__ __launch_bounds__(256) void prep_b(const float* __restrict__ pos) {
    prep_body(pos, (NN*HH*16)/2 + blockIdx.x*256 + threadIdx.x);
}

// ---------------------------------------------------------------- kernel 1c
// gather the 1024 query rows per head into dense g_bq.
__global__ __launch_bounds__(256) void qgather(const int* __restrict__ edges) {
    int i = blockIdx.x*256 + threadIdx.x;    // NQ*HH*8 = 32768 uint4 chunks
    int c = i & 7;
    int q = (i >> 3) & (NQ - 1);
    int h = i >> 13;
    int node = edges[q];
    uint4 v = *(const uint4*)((const char*)&g_bpos[((size_t)h*NN + node)*DD] + c*16);
    *(uint4*)((char*)&g_bq[((size_t)h*NQ + q)*DD] + c*16) = v;
}

// ---------------------------------------------------------------- kernel 2
// grid (NROWS/RPB = 32, NPART = 32), 256 threads = 8 warps, occ 2 (128 regs:
// room for ptxas to software-pipeline). Two independent HMMA chains per nt.
__global__ __launch_bounds__(256, 2) void knn_mma() {
    __shared__ __align__(16) char s_mem[2][CT*SROW];   // buf1 aliases queries
    __shared__ float s_pn2[2][CT];

    const int t = threadIdx.x;
    const int w = t >> 5, l = t & 31;
    const int rb = blockIdx.x * RPB;
    const int h  = rb / NQ;               // constant within block
    const int q0 = rb % NQ;
    const int part = blockIdx.y;
    const __nv_bfloat16* bpos = g_bpos + (size_t)h*NN*DD;

    // ---- stage queries (async) into buf1; tile0 (async) into buf0 ----
#pragma unroll
    for (int k = 0; k < 4; k++) {
        int i = t + 256*k;                // RPB*8 = 1024 chunks
        int r = i >> 3, c = i & 7;
        cp16(smem_u32(&s_mem[1][r*SROW + c*16]),
             (const char*)&g_bq[((size_t)h*NQ + q0 + r)*DD] + c*16);
    }
    CP_COMMIT();                          // group A: queries
    STAGE(0, 0);                          // group B: tile0
    CP_WAIT1();                           // queries landed
    __syncthreads();

    // ---- A fragments (16 queries x K=64) from buf1, loaded once ----
    u32 af[4][4];
    {
        u32 abase = smem_u32(s_mem[1]) + (u32)((w*16 + (l & 7) + ((l >> 3) & 1)*8)*SROW
                                               + (l >> 4)*16);
#pragma unroll
        for (int ks = 0; ks < 4; ks++)
            asm volatile("ldmatrix.sync.aligned.m8n8.x4.shared.b16 {%0,%1,%2,%3}, [%4];"
                : "=r"(af[ks][0]), "=r"(af[ks][1]), "=r"(af[ks][2]), "=r"(af[ks][3])
                : "r"(abase + ks*32));
    }
    __syncthreads();                      // all warps done reading queries
    STAGE(1, 1);                          // group C: tile1 overwrites queries
    CP_WAIT1();                           // tile0 landed
    __syncthreads();

    u32 LA[RL], LB[RL];
#pragma unroll
    for (int i = 0; i < RL; i++) { LA[i] = 0u; LB[i] = 0u; }

    const int csel = 2*(l & 3);           // fragment column pair base

#pragma unroll 1
    for (int tile = 0; tile < NTILES; tile++) {
        const int cur = tile & 1;
        const int cb = part*CPART + tile*CT;
        u32 cbase = smem_u32(s_mem[cur]) + (u32)((l & 7)*SROW + (l >> 3)*16);

        float fa_r = 0.f, fb_r = 0.f;     // running max across 4-nt groups
        u32   la_r = 0u,  lb_r = 0u;

#pragma unroll
        for (int nt = 0; nt < CT/8; nt++) {
            u32 b0,b1,b2,b3,b4,b5,b6,b7;
            asm volatile("ldmatrix.sync.aligned.m8n8.x4.shared.b16 {%0,%1,%2,%3}, [%4];"
                : "=r"(b0), "=r"(b1), "=r"(b2), "=r"(b3)
                : "r"(cbase + (u32)(nt*8*SROW)));
            asm volatile("ldmatrix.sync.aligned.m8n8.x4.shared.b16 {%0,%1,%2,%3}, [%4];"
                : "=r"(b4), "=r"(b5), "=r"(b6), "=r"(b7)
                : "r"(cbase + (u32)(nt*8*SROW + 64)));

            int c0 = nt*8 + csel;
            float2 p2 = *(const float2*)&s_pn2[cur][c0];
            // chain A: bias-initialized, K chunks 0-1; chain B: zero, chunks 2-3
            float a0 = p2.x, a1 = p2.y, a2 = p2.x, a3 = p2.y;
            float e0 = 0.f, e1 = 0.f, e2 = 0.f, e3 = 0.f;
#define MMA_STEP(D0, D1, D2, D3, A, x, y)                                        \
            asm volatile("mma.sync.aligned.m16n8k16.row.col.f32.bf16.bf16.f32 "  \
                "{%0,%1,%2,%3}, {%4,%5,%6,%7}, {%8,%9}, {%0,%1,%2,%3};"          \
                : "+f"(D0), "+f"(D1), "+f"(D2), "+f"(D3)                         \
                : "r"(A[0]), "r"(A[1]), "r"(A[2]), "r"(A[3]), "r"(x), "r"(y))
            MMA_STEP(a0, a1, a2, a3, af[0], b0, b1);
            MMA_STEP(e0, e1, e2, e3, af[2], b4, b5);
            MMA_STEP(a0, a1, a2, a3, af[1], b2, b3);
            MMA_STEP(e0, e1, e2, e3, af[3], b6, b7);
#undef MMA_STEP
            float d0 = a0 + e0, d1 = a1 + e1;
            float d2 = a2 + e2, d3 = a3 + e3;

            int i0 = cb + c0;
            u32 low0 = (u32)(16383 - i0);       // ~idx in 14 bits
            u32 low1 = low0 - 1u;

            bool  a01 = (d0 >= d1);             // tie -> lower idx
            float fa = a01 ? d0 : d1;
            u32   la = a01 ? low0 : low1;
            bool  b01 = (d2 >= d3);
            float fb = b01 ? d2 : d3;
            u32   lb = b01 ? low0 : low1;

            if ((nt & 3) == 0) {                // group start: reset carry
                fa_r = fa; la_r = la;
                fb_r = fb; lb_r = lb;
            } else {                            // strict > keeps earlier on tie
                if (fa > fa_r) { fa_r = fa; la_r = la; }
                if (fb > fb_r) { fb_r = fb; lb_r = lb; }
            }
            if ((nt & 3) == 3) {                // group end: one insert per list
                u32 ka = __float2uint_rz(fa_r) * 16384u + la_r;
                INSERT4(LA, ka);
                u32 kb = __float2uint_rz(fb_r) * 16384u + lb_r;
                INSERT4(LB, kb);
            }
        }

        __syncthreads();                  // all warps done reading cur
        if (tile + 2 < NTILES) STAGE(tile + 2, cur);
        if (tile + 1 < NTILES) {
            if (tile + 2 < NTILES) { CP_WAIT1(); } else { CP_WAIT0(); }
            __syncthreads();              // next tile visible to all
        }
    }

    // ---- merge across the 4 quad lanes (cols partitioned by l&3) ----
    const int rowA = rb + w*16 + (l >> 2);      // fragment rows l/4 and l/4+8
    WARP_MERGE(LA, 0);
    WARP_MERGE(LB, 1);
}

// ---------------------------------------------------------------- kernel 2b
// Merge NPART partial top-9 lists -> top-8 excluding self (= max).
__global__ __launch_bounds__(256) void merge_kernel() {
    int gid = blockIdx.x*256 + threadIdx.x;   // row*4 + sub
    int id  = gid >> 2;                       // row = q*HH + h
    int sub = gid & 3;
    if (id >= NQ*HH) return;
    int q = id / HH, h = id % HH;

    u32 L[9];
#pragma unroll
    for (int i = 0; i < 9; i++) L[i] = 0u;

    for (int p = sub*8; p < sub*8 + 8; p++) {
        long base = ((long)(p*NQ + q)*HH + h)*9;
#pragma unroll
        for (int r = 0; r < 9; r++) {
            u32 v = g_pp[base + r];
            INSERT9P(L, v);
        }
    }
    int hp = 0;
    for (int r = 0; r < 9; r++) {
        u32 v = (hp < 9) ? L[hp] : 0u;
        u32 bv = v;
#pragma unroll
        for (int o = 1; o < 4; o <<= 1) {
            u32 ov = __shfl_xor_sync(0xffffffffu, bv, o);
            if (ov > bv) bv = ov;
        }
        if (v == bv) hp++;                    // unique values: one lane pops
        if (sub == 0 && r >= 1) g_knn[id*KK + (r-1)] = 16383 - (int)(bv & 0x3FFFu);
    }
}

// ---------------------------------------------------------------- kernel 3
// One block per edge b; 128 threads = 2 threads (half-rows) per (side,h,k).
__global__ __launch_bounds__(128) void epi_kernel(const float* __restrict__ pos,
                                                  const float* __restrict__ grads,
                                                  const float* __restrict__ adj,
                                                  const float* __restrict__ lw,
                                                  const int* __restrict__ edges,
                                                  float* __restrict__ out) {
    __shared__ float sd[HH*16];
    __shared__ float sl[HH*16];
    __shared__ float sh[HH];

    int b = blockIdx.x, t = threadIdx.x;
    int side = t >> 6;
    int h = (t >> 4) & 3;
    int k = (t >> 1) & 7;
    int half = t & 1;

    int sb = edges[b], db = edges[BB + b];
    int qn = side ? db : sb;
    int gn = side ? sb : db;
    int q  = side ? (BB + b) : b;
    int nb = g_knn[(q*HH + h)*KK + k];

    const float4* qp = (const float4*)(pos   + ((size_t)qn*HH + h)*DD);
    const float4* np = (const float4*)(pos   + ((size_t)nb*HH + h)*DD);
    const float4* gp = (const float4*)(grads + ((size_t)gn*HH + h)*DD);

    float ss = 0.f, cc = 0.f;
#pragma unroll
    for (int j = 0; j < 8; j++) {
        int i = half*8 + j;
        float4 a = qp[i], c = np[i], g4 = gp[i];
        float d0 = a.x - c.x, d1 = a.y - c.y, d2 = a.z - c.z, d3 = a.w - c.w;
        ss += d0*d0 + d1*d1 + d2*d2 + d3*d3;
        cc += d0*g4.x + d1*g4.y + d2*g4.z + d3*g4.w;
    }
    ss += __shfl_xor_sync(0xffffffffu, ss, 1);
    cc += __shfl_xor_sync(0xffffffffu, cc, 1);

    if (half == 0) {
        float dist = sqrtf(ss);
        float adjv = side ? adj[(size_t)sb*NN + nb] : adj[(size_t)nb*NN + db];
        float logit = lw[0]*adjv + cc;
        int slot = h*16 + side*8 + k;
        sd[slot] = dist;
        sl[slot] = logit;
    }
    __syncthreads();

    if (t < HH) {
        float mind = 1.0f;
#pragma unroll
        for (int j = 0; j < 16; j++) mind = fminf(mind, sd[t*16 + j]);
        float num = 0.f;
        float den = 8.f * expf(mind - 1.0f);
#pragma unroll
        for (int j = 0; j < 16; j++) {
            float e = expf(mind - sd[t*16 + j]);
            den += e;
            num += e * sl[t*16 + j];
        }
        sh[t] = num / den;
    }
    __syncthreads();
    if (t == 0) {
        float s = 0.25f * (sh[0] + sh[1] + sh[2] + sh[3]);
        out[b] = 1.f / (1.f + expf(-s));
    }
}

// ---------------------------------------------------------------- launch
extern "C" void kernel_launch(void* const* d_in, const int* in_sizes, int n_in,
                              void* d_out, int out_size) {
    const float* pos   = (const float*)d_in[0];
    const float* grads = (const float*)d_in[1];
    const float* adj   = (const float*)d_in[2];
    const float* lw    = (const float*)d_in[3];
    const int*   edges = (const int*)  d_in[4];
    float* out = (float*)d_out;

    prep_a<<<(NN*HH*16)/2/256, 256>>>(pos);      // knn_mma stays launch #4
    prep_b<<<(NN*HH*16)/2/256, 256>>>(pos);
    qgather<<<(NQ*HH*8)/256, 256>>>(edges);
    knn_mma<<<dim3(NROWS/RPB, NPART), 256>>>();
    merge_kernel<<<(NQ*HH*4 + 255)/256, 256>>>();
    epi_kernel<<<BB, 128>>>(pos, grads, adj, lw, edges, out);
}